// round 14
// baseline (speedup 1.0000x reference)
#include <cuda_runtime.h>
#include <cuda_bf16.h>
#include <cuda_fp16.h>
#include <stdint.h>
#include <math.h>

#define Nn 50000
#define ALPHA 0.1f
#define SLOPE 0.2f
#define Ee 640000

// ---------------- device scratch ----------------
__device__ int   g_incnt[Nn];
__device__ int   g_outcnt[Nn];
__device__ int   g_cursor[Nn];
__device__ int   g_rowptr[Nn + 1];
__device__ int   g_esrc[Ee];

__device__ __half g_x16[Nn * 128];          // LN1/LN2 output, fp16
__device__ __half g_p16[3 * Nn * 128];      // fh16 | ft16 | fe16 gather tables
__device__ __half g_h16a[Nn * 128];
__device__ __half g_h16b[Nn * 128];
__device__ float g_rst[Nn * 128];
__device__ __half g_f1[Nn * 512];           // FFN1 output, fp16
__device__ float g_logits[Ee * 8];          // exp(e)*hn[src]
__device__ float g_invden[Nn * 8];
__device__ float g_headnorm[Nn];
__device__ float g_tailnorm[Nn];

__device__ __half g_pw16[3 * 128 * 128];
__device__ __half g_w116[512 * 128];
__device__ __half g_w216[128 * 512];

// ---------------- fused weight convert + counter zero ----------------
__global__ void k_splitall(const float* __restrict__ wa, const float* __restrict__ wb,
                           const float* __restrict__ wc, const float* __restrict__ wd,
                           const float* __restrict__ we) {
    int i = blockIdx.x * blockDim.x + threadIdx.x;
    if (i >= 230224) return;
    if (i >= 180224) {
        int j = i - 180224;
        g_incnt[j] = 0; g_outcnt[j] = 0; g_cursor[j] = 0;
        return;
    }
    const float* s; __half* hi; int off;
    if (i < 16384)        { s = wa; off = i;          hi = g_pw16; }
    else if (i < 32768)   { s = wb; off = i - 16384;  hi = g_pw16 + 16384; }
    else if (i < 49152)   { s = wc; off = i - 32768;  hi = g_pw16 + 32768; }
    else if (i < 114688)  { s = wd; off = i - 49152;  hi = g_w116; }
    else                  { s = we; off = i - 114688; hi = g_w216; }
    hi[off] = __float2half_rn(s[off]);
}

// ---------------- CSR build ----------------
__global__ void k_hist(const int* __restrict__ src, const int* __restrict__ dst, int E) {
    int e = blockIdx.x * blockDim.x + threadIdx.x;
    if (e < E) {
        atomicAdd(&g_incnt[dst[e]], 1);
        atomicAdd(&g_outcnt[src[e]], 1);
    }
}
// single-block full scan + node scalars (validated in R12)
__global__ void k_scanall() {
    __shared__ int s[1024];
    int t = threadIdx.x;
    const int PER = 49;   // 1024*49 = 50176 >= Nn
    int b0 = t * PER;
    int e0 = b0 + PER; if (e0 > Nn) e0 = Nn;
    int sum = 0;
    for (int j = b0; j < e0; j++) sum += g_incnt[j];
    s[t] = sum;
    __syncthreads();
    for (int off = 1; off < 1024; off <<= 1) {
        int add = (t >= off) ? s[t - off] : 0;
        __syncthreads();
        s[t] += add;
        __syncthreads();
    }
    int run = s[t] - sum;   // exclusive prefix
    for (int j = b0; j < e0; j++) {
        run += g_incnt[j];
        g_rowptr[j + 1] = run;
        int od = g_outcnt[j]; if (od < 1) od = 1;
        int id = g_incnt[j];  if (id < 1) id = 1;
        g_headnorm[j] = rsqrtf((float)od);
        g_tailnorm[j] = sqrtf((float)id);
    }
    if (t == 0) g_rowptr[0] = 0;
}
__global__ void k_scatter(const int* __restrict__ src, const int* __restrict__ dst, int E) {
    int e = blockIdx.x * blockDim.x + threadIdx.x;
    if (e < E) {
        int d = dst[e];
        int pos = g_rowptr[d] + atomicAdd(&g_cursor[d], 1);
        g_esrc[pos] = src[e];
    }
}

// ---------------- helpers ----------------
__device__ __forceinline__ void storeHalf4(__half* p, float4 v) {
    __half2 a = __floats2half2_rn(v.x, v.y);
    __half2 b = __floats2half2_rn(v.z, v.w);
    uint2 u; u.x = *(unsigned*)&a; u.y = *(unsigned*)&b;
    *(uint2*)p = u;
}
__device__ __forceinline__ float4 h4tof4(uint2 u) {
    float2 f0 = __half22float2(*(__half2*)&u.x);
    float2 f1 = __half22float2(*(__half2*)&u.y);
    float4 r; r.x = f0.x; r.y = f0.y; r.z = f1.x; r.w = f1.y;
    return r;
}
__device__ __forceinline__ void accumh(float4& a, uint2 u, float w) {
    __half2 p0 = *(__half2*)&u.x;
    __half2 p1 = *(__half2*)&u.y;
    float2 f0 = __half22float2(p0);
    float2 f1 = __half22float2(p1);
    a.x = fmaf(f0.x, w, a.x); a.y = fmaf(f0.y, w, a.y);
    a.z = fmaf(f1.x, w, a.z); a.w = fmaf(f1.y, w, a.w);
}

// ---------------- LayerNorm -> fp16 (warp per node) ----------------
__global__ void k_ln(const float* __restrict__ in, const float* __restrict__ g,
                     const float* __restrict__ b) {
    int node = (blockIdx.x * blockDim.x + threadIdx.x) >> 5;
    int lane = threadIdx.x & 31;
    if (node >= Nn) return;
    float4 v = *(const float4*)(in + node * 128 + lane * 4);
    float s  = v.x + v.y + v.z + v.w;
    float s2 = v.x * v.x + v.y * v.y + v.z * v.z + v.w * v.w;
    #pragma unroll
    for (int o = 16; o > 0; o >>= 1) {
        s  += __shfl_xor_sync(0xffffffffu, s, o);
        s2 += __shfl_xor_sync(0xffffffffu, s2, o);
    }
    float mu  = s * (1.0f / 128.0f);
    float var = s2 * (1.0f / 128.0f) - mu * mu;
    float inv = rsqrtf(var + 1e-5f);
    float4 gv = *(const float4*)(g + lane * 4);
    float4 bv = *(const float4*)(b + lane * 4);
    float4 o4;
    o4.x = (v.x - mu) * inv * gv.x + bv.x;
    o4.y = (v.y - mu) * inv * gv.y + bv.y;
    o4.z = (v.z - mu) * inv * gv.z + bv.z;
    o4.w = (v.w - mu) * inv * gv.w + bv.w;
    storeHalf4(g_x16 + node * 128 + lane * 4, o4);
}

// ---------------- fp16 tensor-core GEMM: M64 tile, 3 CTAs/SM ----------------
__device__ __forceinline__ void mma16816(float* c, const unsigned* a, unsigned b0, unsigned b1) {
    asm("mma.sync.aligned.m16n8k16.row.col.f32.f16.f16.f32 "
        "{%0,%1,%2,%3}, {%4,%5,%6,%7}, {%8,%9}, {%0,%1,%2,%3};"
        : "+f"(c[0]), "+f"(c[1]), "+f"(c[2]), "+f"(c[3])
        : "r"(a[0]), "r"(a[1]), "r"(a[2]), "r"(a[3]), "r"(b0), "r"(b1));
}
__device__ __forceinline__ void ldsm4(unsigned* r, const void* p) {
    unsigned a = (unsigned)__cvta_generic_to_shared(p);
    asm volatile("ldmatrix.sync.aligned.m8n8.x4.shared.b16 {%0,%1,%2,%3}, [%4];"
        : "=r"(r[0]), "=r"(r[1]), "=r"(r[2]), "=r"(r[3]) : "r"(a));
}
__device__ __forceinline__ void cpasync16(void* smem, const void* g, bool p) {
    unsigned sa = (unsigned)__cvta_generic_to_shared(smem);
    int sz = p ? 16 : 0;
    asm volatile("cp.async.cg.shared.global [%0], [%1], 16, %2;" :: "r"(sa), "l"(g), "r"(sz));
}
__device__ __forceinline__ void cpcommit() { asm volatile("cp.async.commit_group;"); }
template<int N> __device__ __forceinline__ void cpwait() {
    asm volatile("cp.async.wait_group %0;" :: "n"(N));
}

#define STAGES 4
#define AST (64 * 40)
#define BST (128 * 40)
#define MMA_SMEM_BYTES (STAGES * (AST + BST) * 2)

// mode 0: O16[y] = half(acc)
// mode 1: O16 = half(relu(acc + e1[col]))
// mode 2: Cf = acc + e1[col] + e2[row*128+col]
__global__ void __launch_bounds__(256, 3) k_mma(
    const __half* __restrict__ A, const __half* __restrict__ W,
    int K, int mode, int ldc, int wyStride, int o16yStride, int colPerY,
    const float* __restrict__ e1, const float* __restrict__ e2,
    float* __restrict__ Cf, __half* __restrict__ O16)
{
    extern __shared__ __align__(16) __half sm[];
    __half* AsS = sm;                        // [STAGES][64*40]
    __half* BsS = sm + STAGES * AST;         // [STAGES][128*40]

    const int t = threadIdx.x;
    const int lt = t & 31, wid = t >> 5;
    const int wm = wid & 3, wn = wid >> 2;   // 4 M-warps x 2 N-warps
    const int r4 = lt >> 2, tig = lt & 3;
    const int row0 = blockIdx.x * 64;

    const __half* Wg = W + (size_t)blockIdx.y * wyStride;
    __half* C16 = O16 ? O16 + (size_t)blockIdx.y * o16yStride : O16;
    const int col0 = blockIdx.y * colPerY;

    const int NCH = K >> 5;

    float c[8][4];
    #pragma unroll
    for (int j = 0; j < 8; j++)
        #pragma unroll
        for (int k = 0; k < 4; k++) c[j][k] = 0.f;

    auto loadChunk = [&](int cidx, int st) {
        int kc = cidx << 5;
        __half* Ab = AsS + st * AST;
        __half* Bb = BsS + st * BST;
        {   // A: 64 rows x 32 halfs = 2048 halfs = 256 thr x 8 halfs
            int row = t >> 2, q = t & 3;
            int gr = row0 + row;
            cpasync16(Ab + row * 40 + q * 8, A + (size_t)gr * K + kc + q * 8, gr < Nn);
        }
        #pragma unroll
        for (int i = 0; i < 2; i++) {   // B: 128 rows x 32 halfs
            int lin = t + i * 256;
            int row = lin >> 2, q = lin & 3;
            cpasync16(Bb + row * 40 + q * 8, Wg + (size_t)row * K + kc + q * 8, true);
        }
    };

    loadChunk(0, 0); cpcommit();
    if (NCH > 1) { loadChunk(1, 1); } cpcommit();
    if (NCH > 2) { loadChunk(2, 2); } cpcommit();

    const int rb0 = wm * 16;
    for (int cc = 0; cc < NCH; cc++) {
        cpwait<2>();
        __syncthreads();
        if (cc + 3 < NCH)
            loadChunk(cc + 3, (cc + 3) & (STAGES - 1));
        cpcommit();
        const __half* Asb = AsS + (cc & (STAGES - 1)) * AST;
        const __half* Bsb = BsS + (cc & (STAGES - 1)) * BST;

        unsigned a0[2][4];
        #pragma unroll
        for (int ks = 0; ks < 2; ks++)
            ldsm4(a0[ks], Asb + (rb0 + (lt & 15)) * 40 + ks * 16 + ((lt >> 4) * 8));
        #pragma unroll
        for (int ks = 0; ks < 2; ks++) {
            #pragma unroll
            for (int ntp = 0; ntp < 4; ntp++) {
                unsigned br[4];
                int nrow = wn * 64 + ntp * 16 + ((lt >> 4) << 3) + (lt & 7);
                ldsm4(br, Bsb + nrow * 40 + ks * 16 + (((lt >> 3) & 1) * 8));
                mma16816(c[2 * ntp],     a0[ks], br[0], br[1]);
                mma16816(c[2 * ntp + 1], a0[ks], br[2], br[3]);
            }
        }
    }

    // epilogue: warp covers rows row0+wm*16 .. +15, cols wn*64 .. +63
    #pragma unroll
    for (int half = 0; half < 2; half++) {
        int r = row0 + wm * 16 + r4 + half * 8;
        if (r >= Nn) continue;
        if (mode == 0) {
            #pragma unroll
            for (int nt = 0; nt < 8; nt++) {
                int col = wn * 64 + nt * 8 + tig * 2;
                *(__half2*)(C16 + (size_t)r * ldc + col) =
                    __floats2half2_rn(c[nt][half * 2], c[nt][half * 2 + 1]);
            }
        } else if (mode == 1) {
            #pragma unroll
            for (int nt = 0; nt < 8; nt++) {
                int col = col0 + wn * 64 + nt * 8 + tig * 2;
                float v0 = fmaxf(c[nt][half * 2] + e1[col], 0.f);
                float v1 = fmaxf(c[nt][half * 2 + 1] + e1[col + 1], 0.f);
                *(__half2*)(C16 + (size_t)r * ldc + col) = __floats2half2_rn(v0, v1);
            }
        } else {
            #pragma unroll
            for (int nt = 0; nt < 8; nt++) {
                int col = wn * 64 + nt * 8 + tig * 2;
                float2 o;
                o.x = c[nt][half * 2] + e1[col] + e2[(size_t)r * 128 + col];
                o.y = c[nt][half * 2 + 1] + e1[col + 1] + e2[(size_t)r * 128 + col + 1];
                *(float2*)(Cf + (size_t)r * ldc + col) = o;
            }
        }
    }
}

// ---------------- fused attention + softmax + hop0, single pass, half2 math ----------------
__global__ void k_attnhop(const float* __restrict__ attn, __half* __restrict__ hout) {
    int node = (blockIdx.x * blockDim.x + threadIdx.x) >> 5;
    int lane = threadIdx.x & 31;
    if (node >= Nn) return;
    const __half* fh16 = g_p16;
    const __half* ft16 = g_p16 + (size_t)Nn * 128;
    const __half* fe16 = g_p16 + (size_t)2 * Nn * 128;
    int beg = g_rowptr[node], end = g_rowptr[node + 1];
    int h = lane >> 2;
    uint2 ftu = *(const uint2*)(ft16 + (size_t)node * 128 + lane * 4);
    __half2 fta = *(__half2*)&ftu.x;
    __half2 ftb = *(__half2*)&ftu.y;
    const __half2 sl2 = __float2half2_rn(SLOPE);
    float4 av = *(const float4*)(attn + lane * 4);
    float hnn = g_headnorm[node];
    float scale = log1pf((float)g_incnt[node]) * (1.0f / 16.0f) * hnn;
    float4 acc0 = make_float4(0.f, 0.f, 0.f, 0.f);
    float4 acc1 = make_float4(0.f, 0.f, 0.f, 0.f);
    float sum = 0.f;
    int p = beg;
    for (; p + 2 <= end; p += 2) {
        int s0 = g_esrc[p];
        int s1 = g_esrc[p + 1];
        float hs0 = g_headnorm[s0], hs1 = g_headnorm[s1];
        uint2 u0 = *(const uint2*)(fh16 + (size_t)s0 * 128 + lane * 4);
        uint2 u1 = *(const uint2*)(fh16 + (size_t)s1 * 128 + lane * 4);
        uint2 f0 = *(const uint2*)(fe16 + (size_t)s0 * 128 + lane * 4);
        uint2 f1 = *(const uint2*)(fe16 + (size_t)s1 * 128 + lane * 4);
        __half2 p0a = __hmul2(*(__half2*)&u0.x, fta);
        __half2 p0b = __hmul2(*(__half2*)&u0.y, ftb);
        __half2 p1a = __hmul2(*(__half2*)&u1.x, fta);
        __half2 p1b = __hmul2(*(__half2*)&u1.y, ftb);
        p0a = __hmax2(p0a, __hmul2(p0a, sl2));
        p0b = __hmax2(p0b, __hmul2(p0b, sl2));
        p1a = __hmax2(p1a, __hmul2(p1a, sl2));
        p1b = __hmax2(p1b, __hmul2(p1b, sl2));
        float2 q0a = __half22float2(p0a), q0b = __half22float2(p0b);
        float2 q1a = __half22float2(p1a), q1b = __half22float2(p1b);
        float ts0 = q0a.x * av.x + q0a.y * av.y + q0b.x * av.z + q0b.y * av.w;
        float ts1 = q1a.x * av.x + q1a.y * av.y + q1b.x * av.z + q1b.y * av.w;
        ts0 += __shfl_xor_sync(0xffffffffu, ts0, 1);
        ts1 += __shfl_xor_sync(0xffffffffu, ts1, 1);
        ts0 += __shfl_xor_sync(0xffffffffu, ts0, 2);
        ts1 += __shfl_xor_sync(0xffffffffu, ts1, 2);
        float w0 = __expf(ts0 * scale * hs0);
        float w1 = __expf(ts1 * scale * hs1);
        sum += w0 + w1;
        float wh0 = w0 * hs0, wh1 = w1 * hs1;
        if ((lane & 3) == 0) { g_logits[p * 8 + h] = wh0; g_logits[(p + 1) * 8 + h] = wh1; }
        accumh(acc0, f0, wh0);
        accumh(acc1, f1, wh1);
    }
    if (p < end) {
        int s0 = g_esrc[p];
        float hs0 = g_headnorm[s0];
        uint2 u0 = *(const uint2*)(fh16 + (size_t)s0 * 128 + lane * 4);
        uint2 f0 = *(const uint2*)(fe16 + (size_t)s0 * 128 + lane * 4);
        __half2 p0a = __hmul2(*(__half2*)&u0.x, fta);
        __half2 p0b = __hmul2(*(__half2*)&u0.y, ftb);
        p0a = __hmax2(p0a, __hmul2(p0a, sl2));
        p0b = __hmax2(p0b, __hmul2(p0b, sl2));
        float2 q0a = __half22float2(p0a), q0b = __half22float2(p0b);
        float ts = q0a.x * av.x + q0a.y * av.y + q0b.x * av.z + q0b.y * av.w;
        ts += __shfl_xor_sync(0xffffffffu, ts, 1);
        ts += __shfl_xor_sync(0xffffffffu, ts, 2);
        float w0 = __expf(ts * scale * hs0);
        sum += w0;
        float wh0 = w0 * hs0;
        if ((lane & 3) == 0) g_logits[p * 8 + h] = wh0;
        accumh(acc0, f0, wh0);
    }
    float inv = 1.0f / sum;
    if ((lane & 3) == 0) g_invden[node * 8 + h] = inv;
    float wf = inv * (1.0f - ALPHA) * g_tailnorm[node];
    float4 fev = h4tof4(*(const uint2*)(fe16 + (size_t)node * 128 + lane * 4));
    float af = ALPHA * hnn;
    float4 o;
    o.x = (acc0.x + acc1.x) * wf + af * fev.x;
    o.y = (acc0.y + acc1.y) * wf + af * fev.y;
    o.z = (acc0.z + acc1.z) * wf + af * fev.z;
    o.w = (acc0.w + acc1.w) * wf + af * fev.w;
    storeHalf4(hout + (size_t)node * 128 + lane * 4, o);
}

// ---------------- PPR diffusion hop (warp per dst node, 8-deep MLP) ----------------
__global__ void k_diff(const __half* __restrict__ hin, __half* __restrict__ hout,
                       const float* __restrict__ feat, const float* __restrict__ lg,
                       const float* __restrict__ lb, float* __restrict__ rst, int finalize) {
    int node = (blockIdx.x * blockDim.x + threadIdx.x) >> 5;
    int lane = threadIdx.x & 31;
    if (node >= Nn) return;
    const __half* fe16 = g_p16 + (size_t)2 * Nn * 128;
    int beg = g_rowptr[node], end = g_rowptr[node + 1];
    int h = lane >> 2;
    float4 a0 = make_float4(0.f, 0.f, 0.f, 0.f);
    float4 a1 = make_float4(0.f, 0.f, 0.f, 0.f);
    float4 a2 = make_float4(0.f, 0.f, 0.f, 0.f);
    float4 a3 = make_float4(0.f, 0.f, 0.f, 0.f);
    int p = beg;
    for (; p + 8 <= end; p += 8) {
        int s0 = g_esrc[p],     s1 = g_esrc[p + 1], s2 = g_esrc[p + 2], s3 = g_esrc[p + 3];
        int s4 = g_esrc[p + 4], s5 = g_esrc[p + 5], s6 = g_esrc[p + 6], s7 = g_esrc[p + 7];
        float w0 = g_logits[p * 8 + h];
        float w1 = g_logits[(p + 1) * 8 + h];
        float w2 = g_logits[(p + 2) * 8 + h];
        float w3 = g_logits[(p + 3) * 8 + h];
        float w4 = g_logits[(p + 4) * 8 + h];
        float w5 = g_logits[(p + 5) * 8 + h];
        float w6 = g_logits[(p + 6) * 8 + h];
        float w7 = g_logits[(p + 7) * 8 + h];
        uint2 u0 = *(const uint2*)(hin + (size_t)s0 * 128 + lane * 4);
        uint2 u1 = *(const uint2*)(hin + (size_t)s1 * 128 + lane * 4);
        uint2 u2 = *(const uint2*)(hin + (size_t)s2 * 128 + lane * 4);
        uint2 u3 = *(const uint2*)(hin + (size_t)s3 * 128 + lane * 4);
        uint2 u4 = *(const uint2*)(hin + (size_t)s4 * 128 + lane * 4);
        uint2 u5 = *(const uint2*)(hin + (size_t)s5 * 128 + lane * 4);
        uint2 u6 = *(const uint2*)(hin + (size_t)s6 * 128 + lane * 4);
        uint2 u7 = *(const uint2*)(hin + (size_t)s7 * 128 + lane * 4);
        accumh(a0, u0, w0); accumh(a1, u1, w1);
        accumh(a2, u2, w2); accumh(a3, u3, w3);
        accumh(a0, u4, w4); accumh(a1, u5, w5);
        accumh(a2, u6, w6); accumh(a3, u7, w7);
    }
    for (; p + 4 <= end; p += 4) {
        int s0 = g_esrc[p], s1 = g_esrc[p + 1], s2 = g_esrc[p + 2], s3 = g_esrc[p + 3];
        float w0 = g_logits[p * 8 + h];
        float w1 = g_logits[(p + 1) * 8 + h];
        float w2 = g_logits[(p + 2) * 8 + h];
        float w3 = g_logits[(p + 3) * 8 + h];
        uint2 u0 = *(const uint2*)(hin + (size_t)s0 * 128 + lane * 4);
        uint2 u1 = *(const uint2*)(hin + (size_t)s1 * 128 + lane * 4);
        uint2 u2 = *(const uint2*)(hin + (size_t)s2 * 128 + lane * 4);
        uint2 u3 = *(const uint2*)(hin + (size_t)s3 * 128 + lane * 4);
        accumh(a0, u0, w0); accumh(a1, u1, w1);
        accumh(a2, u2, w2); accumh(a3, u3, w3);
    }
    for (; p < end; p++) {
        int s0 = g_esrc[p];
        float w0 = g_logits[p * 8 + h];
        uint2 u0 = *(const uint2*)(hin + (size_t)s0 * 128 + lane * 4);
        accumh(a0, u0, w0);
    }
    float wf = g_invden[node * 8 + h] * (1.0f - ALPHA) * g_tailnorm[node];
    float4 fev = h4tof4(*(const uint2*)(fe16 + (size_t)node * 128 + lane * 4));
    float af = ALPHA * g_headnorm[node];
    float4 o;
    o.x = (a0.x + a1.x + a2.x + a3.x) * wf + af * fev.x;
    o.y = (a0.y + a1.y + a2.y + a3.y) * wf + af * fev.y;
    o.z = (a0.z + a1.z + a2.z + a3.z) * wf + af * fev.z;
    o.w = (a0.w + a1.w + a2.w + a3.w) * wf + af * fev.w;
    if (!finalize) {
        storeHalf4(hout + (size_t)node * 128 + lane * 4, o);
        return;
    }
    float4 fv = *(const float4*)(feat + (size_t)node * 128 + lane * 4);
    float4 v;
    v.x = o.x + fv.x; v.y = o.y + fv.y; v.z = o.z + fv.z; v.w = o.w + fv.w;
    *(float4*)(rst + (size_t)node * 128 + lane * 4) = v;
    float s  = v.x + v.y + v.z + v.w;
    float s2 = v.x * v.x + v.y * v.y + v.z * v.z + v.w * v.w;
    #pragma unroll
    for (int off = 16; off > 0; off >>= 1) {
        s  += __shfl_xor_sync(0xffffffffu, s, off);
        s2 += __shfl_xor_sync(0xffffffffu, s2, off);
    }
    float mu  = s * (1.0f / 128.0f);
    float var = s2 * (1.0f / 128.0f) - mu * mu;
    float inv = rsqrtf(var + 1e-5f);
    float4 gv = *(const float4*)(lg + lane * 4);
    float4 bv = *(const float4*)(lb + lane * 4);
    float4 o4;
    o4.x = (v.x - mu) * inv * gv.x + bv.x;
    o4.y = (v.y - mu) * inv * gv.y + bv.y;
    o4.z = (v.z - mu) * inv * gv.z + bv.z;
    o4.w = (v.w - mu) * inv * gv.w + bv.w;
    storeHalf4(g_x16 + (size_t)node * 128 + lane * 4, o4);
}

// ---------------- launch ----------------
static void* symv(const void* s) { void* p = nullptr; cudaGetSymbolAddress(&p, s); return p; }

extern "C" void kernel_launch(void* const* d_in, const int* in_sizes, int n_in,
                              void* d_out, int out_size) {
    const float* feat  = (const float*)d_in[0];
    const int*   src   = (const int*)d_in[1];
    const int*   dst   = (const int*)d_in[2];
    const float* w_head = (const float*)d_in[3];
    const float* w_tail = (const float*)d_in[4];
    const float* w_ent  = (const float*)d_in[5];
    const float* attn   = (const float*)d_in[6];
    const float* ln1_g  = (const float*)d_in[7];
    const float* ln1_b  = (const float*)d_in[8];
    const float* ln2_g  = (const float*)d_in[9];
    const float* ln2_b  = (const float*)d_in[10];
    const float* ff_w1  = (const float*)d_in[11];
    const float* ff_b1  = (const float*)d_in[12];
    const float* ff_w2  = (const float*)d_in[13];
    const float* ff_b2  = (const float*)d_in[14];
    int E = in_sizes[1];

    __half* p_x16  = (__half*)symv(g_x16);
    __half* p_pw   = (__half*)symv(g_pw16);
    __half* p_w1   = (__half*)symv(g_w116);
    __half* p_w2   = (__half*)symv(g_w216);
    __half* p_f1   = (__half*)symv(g_f1);
    __half* p_p16  = (__half*)symv(g_p16);
    __half* p_ha   = (__half*)symv(g_h16a);
    __half* p_hb   = (__half*)symv(g_h16b);
    float*  p_rst  = (float*)symv(g_rst);
    float*  out    = (float*)d_out;

    static int smemSet = 0;
    if (!smemSet) {
        cudaFuncSetAttribute(k_mma, cudaFuncAttributeMaxDynamicSharedMemorySize, MMA_SMEM_BYTES);
        smemSet = 1;
    }

    const int TB = 256;
    int gE  = (E + TB - 1) / TB;
    int gW  = (Nn * 32 + TB - 1) / TB;
    int gM  = (Nn + 63) / 64;                // 782 row blocks (M64 tile)

    // #1 weight convert + zero, #2 LN1, #3 hist — projection GEMM at #4 (ncu window)
    k_splitall<<<(230224 + 255) / 256, 256>>>(w_head, w_tail, w_ent, ff_w1, ff_w2);
    k_ln<<<gW, TB>>>(feat, ln1_g, ln1_b);
    k_hist<<<gE, TB>>>(src, dst, E);
    // #4: all 3 projections in one launch (pure fp16 outputs)
    k_mma<<<dim3(gM, 3), 256, MMA_SMEM_BYTES>>>(p_x16, p_pw,
                                128, 0, 128, 128 * 128, Nn * 128, 0,
                                nullptr, nullptr, nullptr, p_p16);
    // CSR build (rest)
    k_scanall<<<1, 1024>>>();
    k_scatter<<<gE, TB>>>(src, dst, E);

    // single-pass fused attention + softmax + hop0
    k_attnhop<<<gW, TB>>>(attn, p_ha);

    // hops 1-4 (hop 4 fuses rst + LN2)
    k_diff<<<gW, TB>>>(p_ha, p_hb, nullptr, nullptr, nullptr, nullptr, 0);
    k_diff<<<gW, TB>>>(p_hb, p_ha, nullptr, nullptr, nullptr, nullptr, 0);
    k_diff<<<gW, TB>>>(p_ha, p_hb, nullptr, nullptr, nullptr, nullptr, 0);
    k_diff<<<gW, TB>>>(p_hb, p_ha, feat, ln2_g, ln2_b, p_rst, 1);

    // FFN1: 4 col-slabs, relu+bias -> fp16 f1
    k_mma<<<dim3(gM, 4), 256, MMA_SMEM_BYTES>>>(p_x16, p_w1,
                                128, 1, 512, 128 * 128, 0, 128,
                                ff_b1, nullptr, nullptr, p_f1);
    // FFN2: K=512, + bias + residual -> fp32 out
    k_mma<<<dim3(gM, 1), 256, MMA_SMEM_BYTES>>>(p_f1, p_w2,
                                512, 2, 128, 0, 0, 0,
                                ff_b2, p_rst, out, nullptr);
}

// round 15
// speedup vs baseline: 1.4750x; 1.4750x over previous
#include <cuda_runtime.h>
#include <cuda_bf16.h>
#include <cuda_fp16.h>
#include <stdint.h>
#include <math.h>

#define Nn 50000
#define ALPHA 0.1f
#define SLOPE 0.2f
#define Ee 640000

// ---------------- device scratch ----------------
__device__ int   g_incnt[Nn];
__device__ int   g_outcnt[Nn];
__device__ int   g_cursor[Nn];
__device__ int   g_rowptr[Nn + 1];
__device__ int   g_boff[128];
__device__ int   g_bsums[128];
__device__ int   g_esrc[Ee];

__device__ __half g_x16[Nn * 128];          // LN1/LN2 output, fp16
__device__ __half g_p16[3 * Nn * 128];      // fh16 | ft16 | fe16 gather tables
__device__ __half g_h16a[Nn * 128];
__device__ __half g_h16b[Nn * 128];
__device__ float g_rst[Nn * 128];
__device__ __half g_f1[Nn * 512];           // FFN1 output, fp16
__device__ __half g_logits[Ee * 8];         // exp(e)*hn[src], fp16
__device__ float g_invden[Nn * 8];
__device__ float g_headnorm[Nn];
__device__ float g_tailnorm[Nn];

__device__ __half g_pw16[3 * 128 * 128];
__device__ __half g_w116[512 * 128];
__device__ __half g_w216[128 * 512];

// ---------------- fused weight convert + counter zero ----------------
__global__ void k_splitall(const float* __restrict__ wa, const float* __restrict__ wb,
                           const float* __restrict__ wc, const float* __restrict__ wd,
                           const float* __restrict__ we) {
    int i = blockIdx.x * blockDim.x + threadIdx.x;
    if (i >= 230224) return;
    if (i >= 180224) {
        int j = i - 180224;
        g_incnt[j] = 0; g_outcnt[j] = 0; g_cursor[j] = 0;
        return;
    }
    const float* s; __half* hi; int off;
    if (i < 16384)        { s = wa; off = i;          hi = g_pw16; }
    else if (i < 32768)   { s = wb; off = i - 16384;  hi = g_pw16 + 16384; }
    else if (i < 49152)   { s = wc; off = i - 32768;  hi = g_pw16 + 32768; }
    else if (i < 114688)  { s = wd; off = i - 49152;  hi = g_w116; }
    else                  { s = we; off = i - 114688; hi = g_w216; }
    hi[off] = __float2half_rn(s[off]);
}

// ---------------- CSR build ----------------
__global__ void k_hist(const int* __restrict__ src, const int* __restrict__ dst, int E) {
    int e = blockIdx.x * blockDim.x + threadIdx.x;
    if (e < E) {
        atomicAdd(&g_incnt[dst[e]], 1);
        atomicAdd(&g_outcnt[src[e]], 1);
    }
}
__global__ void k_scan1() {
    __shared__ int s[512];
    int t = threadIdx.x;
    int i = blockIdx.x * 512 + t;
    int v = (i < Nn) ? g_incnt[i] : 0;
    s[t] = v;
    __syncthreads();
    for (int off = 1; off < 512; off <<= 1) {
        int add = (t >= off) ? s[t - off] : 0;
        __syncthreads();
        s[t] += add;
        __syncthreads();
    }
    if (i < Nn) g_rowptr[i + 1] = s[t];
    if (t == 511) g_bsums[blockIdx.x] = s[511];
}
__global__ void k_scan2() {
    const int NB = (Nn + 511) / 512;
    __shared__ int s[128];
    int t = threadIdx.x;
    int v = (t < NB) ? g_bsums[t] : 0;
    s[t] = v;
    __syncthreads();
    for (int off = 1; off < 128; off <<= 1) {
        int add = (t >= off) ? s[t - off] : 0;
        __syncthreads();
        s[t] += add;
        __syncthreads();
    }
    g_boff[t] = s[t] - v;
}
__global__ void k_scan3ns() {
    int i = blockIdx.x * blockDim.x + threadIdx.x;
    if (i < Nn) {
        g_rowptr[i + 1] += g_boff[i >> 9];
        int od = g_outcnt[i]; if (od < 1) od = 1;
        int id = g_incnt[i];  if (id < 1) id = 1;
        g_headnorm[i] = rsqrtf((float)od);
        g_tailnorm[i] = sqrtf((float)id);
    }
    if (i == 0) g_rowptr[0] = 0;
}
__global__ void k_scatter(const int* __restrict__ src, const int* __restrict__ dst, int E) {
    int e = blockIdx.x * blockDim.x + threadIdx.x;
    if (e < E) {
        int d = dst[e];
        int pos = g_rowptr[d] + atomicAdd(&g_cursor[d], 1);
        g_esrc[pos] = src[e];
    }
}

// ---------------- helpers ----------------
__device__ __forceinline__ void storeHalf4(__half* p, float4 v) {
    __half2 a = __floats2half2_rn(v.x, v.y);
    __half2 b = __floats2half2_rn(v.z, v.w);
    uint2 u; u.x = *(unsigned*)&a; u.y = *(unsigned*)&b;
    *(uint2*)p = u;
}
__device__ __forceinline__ float4 h4tof4(uint2 u) {
    float2 f0 = __half22float2(*(__half2*)&u.x);
    float2 f1 = __half22float2(*(__half2*)&u.y);
    float4 r; r.x = f0.x; r.y = f0.y; r.z = f1.x; r.w = f1.y;
    return r;
}
__device__ __forceinline__ void accumh(float4& a, uint2 u, float w) {
    __half2 p0 = *(__half2*)&u.x;
    __half2 p1 = *(__half2*)&u.y;
    float2 f0 = __half22float2(p0);
    float2 f1 = __half22float2(p1);
    a.x = fmaf(f0.x, w, a.x); a.y = fmaf(f0.y, w, a.y);
    a.z = fmaf(f1.x, w, a.z); a.w = fmaf(f1.y, w, a.w);
}

// ---------------- LayerNorm -> fp16 (warp per node) ----------------
__global__ void k_ln(const float* __restrict__ in, const float* __restrict__ g,
                     const float* __restrict__ b) {
    int node = (blockIdx.x * blockDim.x + threadIdx.x) >> 5;
    int lane = threadIdx.x & 31;
    if (node >= Nn) return;
    float4 v = *(const float4*)(in + node * 128 + lane * 4);
    float s  = v.x + v.y + v.z + v.w;
    float s2 = v.x * v.x + v.y * v.y + v.z * v.z + v.w * v.w;
    #pragma unroll
    for (int o = 16; o > 0; o >>= 1) {
        s  += __shfl_xor_sync(0xffffffffu, s, o);
        s2 += __shfl_xor_sync(0xffffffffu, s2, o);
    }
    float mu  = s * (1.0f / 128.0f);
    float var = s2 * (1.0f / 128.0f) - mu * mu;
    float inv = rsqrtf(var + 1e-5f);
    float4 gv = *(const float4*)(g + lane * 4);
    float4 bv = *(const float4*)(b + lane * 4);
    float4 o4;
    o4.x = (v.x - mu) * inv * gv.x + bv.x;
    o4.y = (v.y - mu) * inv * gv.y + bv.y;
    o4.z = (v.z - mu) * inv * gv.z + bv.z;
    o4.w = (v.w - mu) * inv * gv.w + bv.w;
    storeHalf4(g_x16 + node * 128 + lane * 4, o4);
}

// ---------------- fp16 tensor-core GEMM (R13 proven M128 config) ----------------
__device__ __forceinline__ void mma16816(float* c, const unsigned* a, unsigned b0, unsigned b1) {
    asm("mma.sync.aligned.m16n8k16.row.col.f32.f16.f16.f32 "
        "{%0,%1,%2,%3}, {%4,%5,%6,%7}, {%8,%9}, {%0,%1,%2,%3};"
        : "+f"(c[0]), "+f"(c[1]), "+f"(c[2]), "+f"(c[3])
        : "r"(a[0]), "r"(a[1]), "r"(a[2]), "r"(a[3]), "r"(b0), "r"(b1));
}
__device__ __forceinline__ void ldsm4(unsigned* r, const void* p) {
    unsigned a = (unsigned)__cvta_generic_to_shared(p);
    asm volatile("ldmatrix.sync.aligned.m8n8.x4.shared.b16 {%0,%1,%2,%3}, [%4];"
        : "=r"(r[0]), "=r"(r[1]), "=r"(r[2]), "=r"(r[3]) : "r"(a));
}
__device__ __forceinline__ void cpasync16(void* smem, const void* g, bool p) {
    unsigned sa = (unsigned)__cvta_generic_to_shared(smem);
    int sz = p ? 16 : 0;
    asm volatile("cp.async.cg.shared.global [%0], [%1], 16, %2;" :: "r"(sa), "l"(g), "r"(sz));
}
__device__ __forceinline__ void cpcommit() { asm volatile("cp.async.commit_group;"); }
template<int N> __device__ __forceinline__ void cpwait() {
    asm volatile("cp.async.wait_group %0;" :: "n"(N));
}

#define STAGES 4
#define STAGE_ELEMS (128 * 40)
#define MMA_SMEM_BYTES (STAGES * STAGE_ELEMS * 2 * 2)

// mode 0: O16[y] = half(acc)
// mode 1: O16 = half(relu(acc + e1[col]))
// mode 2: Cf = acc + e1[col] + e2[row*128+col]
__global__ void __launch_bounds__(256, 2) k_mma(
    const __half* __restrict__ A, const __half* __restrict__ W,
    int K, int mode, int ldc, int wyStride, int o16yStride, int colPerY,
    const float* __restrict__ e1, const float* __restrict__ e2,
    float* __restrict__ Cf, __half* __restrict__ O16)
{
    extern __shared__ __align__(16) __half sm[];
    __half* AsS = sm;
    __half* BsS = sm + STAGES * STAGE_ELEMS;

    const int t = threadIdx.x;
    const int lt = t & 31, wid = t >> 5;
    const int wm = wid & 3, wn = wid >> 2;
    const int r4 = lt >> 2, tig = lt & 3;
    const int row0 = blockIdx.x * 128;

    const __half* Wg = W + (size_t)blockIdx.y * wyStride;
    __half* C16 = O16 ? O16 + (size_t)blockIdx.y * o16yStride : O16;
    const int col0 = blockIdx.y * colPerY;

    const int NCH = K >> 5;

    float c[2][8][4];
    #pragma unroll
    for (int i = 0; i < 2; i++)
        #pragma unroll
        for (int j = 0; j < 8; j++)
            #pragma unroll
            for (int k = 0; k < 4; k++) c[i][j][k] = 0.f;

    auto loadChunk = [&](int cidx, int st) {
        int kc = cidx << 5;
        __half* Ab = AsS + st * STAGE_ELEMS;
        __half* Bb = BsS + st * STAGE_ELEMS;
        #pragma unroll
        for (int i = 0; i < 2; i++) {
            int lin = t + i * 256;
            int row = lin >> 2, q = lin & 3;
            int gr = row0 + row;
            cpasync16(Ab + row * 40 + q * 8, A + (size_t)gr * K + kc + q * 8, gr < Nn);
            cpasync16(Bb + row * 40 + q * 8, Wg + (size_t)row * K + kc + q * 8, true);
        }
    };

    loadChunk(0, 0); cpcommit();
    if (NCH > 1) { loadChunk(1, 1); } cpcommit();
    if (NCH > 2) { loadChunk(2, 2); } cpcommit();

    const int rb0 = wm * 32;
    for (int cc = 0; cc < NCH; cc++) {
        cpwait<2>();
        __syncthreads();
        if (cc + 3 < NCH)
            loadChunk(cc + 3, (cc + 3) & (STAGES - 1));
        cpcommit();
        const __half* Asb = AsS + (cc & (STAGES - 1)) * STAGE_ELEMS;
        const __half* Bsb = BsS + (cc & (STAGES - 1)) * STAGE_ELEMS;

        unsigned a0[2][4], a1[2][4];
        #pragma unroll
        for (int ks = 0; ks < 2; ks++) {
            ldsm4(a0[ks], Asb + (rb0 + (lt & 15)) * 40 + ks * 16 + ((lt >> 4) * 8));
            ldsm4(a1[ks], Asb + (rb0 + 16 + (lt & 15)) * 40 + ks * 16 + ((lt >> 4) * 8));
        }
        #pragma unroll
        for (int ks = 0; ks < 2; ks++) {
            #pragma unroll
            for (int ntp = 0; ntp < 4; ntp++) {
                unsigned br[4];
                int nrow = wn * 64 + ntp * 16 + ((lt >> 4) << 3) + (lt & 7);
                ldsm4(br, Bsb + nrow * 40 + ks * 16 + (((lt >> 3) & 1) * 8));
                mma16816(c[0][2 * ntp],     a0[ks], br[0], br[1]);
                mma16816(c[1][2 * ntp],     a1[ks], br[0], br[1]);
                mma16816(c[0][2 * ntp + 1], a0[ks], br[2], br[3]);
                mma16816(c[1][2 * ntp + 1], a1[ks], br[2], br[3]);
            }
        }
    }

    // epilogue
    #pragma unroll
    for (int mt = 0; mt < 2; mt++) {
        #pragma unroll
        for (int half = 0; half < 2; half++) {
            int r = row0 + wm * 32 + mt * 16 + r4 + half * 8;
            if (r >= Nn) continue;
            if (mode == 0) {
                #pragma unroll
                for (int nt = 0; nt < 8; nt++) {
                    int col = wn * 64 + nt * 8 + tig * 2;
                    *(__half2*)(C16 + (size_t)r * ldc + col) =
                        __floats2half2_rn(c[mt][nt][half * 2], c[mt][nt][half * 2 + 1]);
                }
            } else if (mode == 1) {
                #pragma unroll
                for (int nt = 0; nt < 8; nt++) {
                    int col = col0 + wn * 64 + nt * 8 + tig * 2;
                    float v0 = fmaxf(c[mt][nt][half * 2] + e1[col], 0.f);
                    float v1 = fmaxf(c[mt][nt][half * 2 + 1] + e1[col + 1], 0.f);
                    *(__half2*)(C16 + (size_t)r * ldc + col) = __floats2half2_rn(v0, v1);
                }
            } else {
                #pragma unroll
                for (int nt = 0; nt < 8; nt++) {
                    int col = wn * 64 + nt * 8 + tig * 2;
                    float2 o;
                    o.x = c[mt][nt][half * 2] + e1[col] + e2[(size_t)r * 128 + col];
                    o.y = c[mt][nt][half * 2 + 1] + e1[col + 1] + e2[(size_t)r * 128 + col + 1];
                    *(float2*)(Cf + (size_t)r * ldc + col) = o;
                }
            }
        }
    }
}

// ---------------- fused attention + softmax + hop0, single pass, half2 math ----------------
__global__ void k_attnhop(const float* __restrict__ attn, __half* __restrict__ hout) {
    int node = (blockIdx.x * blockDim.x + threadIdx.x) >> 5;
    int lane = threadIdx.x & 31;
    if (node >= Nn) return;
    const __half* fh16 = g_p16;
    const __half* ft16 = g_p16 + (size_t)Nn * 128;
    const __half* fe16 = g_p16 + (size_t)2 * Nn * 128;
    int beg = g_rowptr[node], end = g_rowptr[node + 1];
    int h = lane >> 2;
    uint2 ftu = *(const uint2*)(ft16 + (size_t)node * 128 + lane * 4);
    __half2 fta = *(__half2*)&ftu.x;
    __half2 ftb = *(__half2*)&ftu.y;
    const __half2 sl2 = __float2half2_rn(SLOPE);
    float4 av = *(const float4*)(attn + lane * 4);
    float hnn = g_headnorm[node];
    float scale = log1pf((float)g_incnt[node]) * (1.0f / 16.0f) * hnn;
    float4 acc0 = make_float4(0.f, 0.f, 0.f, 0.f);
    float4 acc1 = make_float4(0.f, 0.f, 0.f, 0.f);
    float sum = 0.f;
    int p = beg;
    for (; p + 2 <= end; p += 2) {
        int s0 = g_esrc[p];
        int s1 = g_esrc[p + 1];
        float hs0 = g_headnorm[s0], hs1 = g_headnorm[s1];
        uint2 u0 = *(const uint2*)(fh16 + (size_t)s0 * 128 + lane * 4);
        uint2 u1 = *(const uint2*)(fh16 + (size_t)s1 * 128 + lane * 4);
        uint2 f0 = *(const uint2*)(fe16 + (size_t)s0 * 128 + lane * 4);
        uint2 f1 = *(const uint2*)(fe16 + (size_t)s1 * 128 + lane * 4);
        __half2 p0a = __hmul2(*(__half2*)&u0.x, fta);
        __half2 p0b = __hmul2(*(__half2*)&u0.y, ftb);
        __half2 p1a = __hmul2(*(__half2*)&u1.x, fta);
        __half2 p1b = __hmul2(*(__half2*)&u1.y, ftb);
        p0a = __hmax2(p0a, __hmul2(p0a, sl2));
        p0b = __hmax2(p0b, __hmul2(p0b, sl2));
        p1a = __hmax2(p1a, __hmul2(p1a, sl2));
        p1b = __hmax2(p1b, __hmul2(p1b, sl2));
        float2 q0a = __half22float2(p0a), q0b = __half22float2(p0b);
        float2 q1a = __half22float2(p1a), q1b = __half22float2(p1b);
        float ts0 = q0a.x * av.x + q0a.y * av.y + q0b.x * av.z + q0b.y * av.w;
        float ts1 = q1a.x * av.x + q1a.y * av.y + q1b.x * av.z + q1b.y * av.w;
        ts0 += __shfl_xor_sync(0xffffffffu, ts0, 1);
        ts1 += __shfl_xor_sync(0xffffffffu, ts1, 1);
        ts0 += __shfl_xor_sync(0xffffffffu, ts0, 2);
        ts1 += __shfl_xor_sync(0xffffffffu, ts1, 2);
        float w0 = __expf(ts0 * scale * hs0);
        float w1 = __expf(ts1 * scale * hs1);
        sum += w0 + w1;
        float wh0 = w0 * hs0, wh1 = w1 * hs1;
        if ((lane & 3) == 0) {
            g_logits[p * 8 + h] = __float2half_rn(wh0);
            g_logits[(p + 1) * 8 + h] = __float2half_rn(wh1);
        }
        accumh(acc0, f0, wh0);
        accumh(acc1, f1, wh1);
    }
    if (p < end) {
        int s0 = g_esrc[p];
        float hs0 = g_headnorm[s0];
        uint2 u0 = *(const uint2*)(fh16 + (size_t)s0 * 128 + lane * 4);
        uint2 f0 = *(const uint2*)(fe16 + (size_t)s0 * 128 + lane * 4);
        __half2 p0a = __hmul2(*(__half2*)&u0.x, fta);
        __half2 p0b = __hmul2(*(__half2*)&u0.y, ftb);
        p0a = __hmax2(p0a, __hmul2(p0a, sl2));
        p0b = __hmax2(p0b, __hmul2(p0b, sl2));
        float2 q0a = __half22float2(p0a), q0b = __half22float2(p0b);
        float ts = q0a.x * av.x + q0a.y * av.y + q0b.x * av.z + q0b.y * av.w;
        ts += __shfl_xor_sync(0xffffffffu, ts, 1);
        ts += __shfl_xor_sync(0xffffffffu, ts, 2);
        float w0 = __expf(ts * scale * hs0);
        sum += w0;
        float wh0 = w0 * hs0;
        if ((lane & 3) == 0) g_logits[p * 8 + h] = __float2half_rn(wh0);
        accumh(acc0, f0, wh0);
    }
    float inv = 1.0f / sum;
    if ((lane & 3) == 0) g_invden[node * 8 + h] = inv;
    float wf = inv * (1.0f - ALPHA) * g_tailnorm[node];
    float4 fev = h4tof4(*(const uint2*)(fe16 + (size_t)node * 128 + lane * 4));
    float af = ALPHA * hnn;
    float4 o;
    o.x = (acc0.x + acc1.x) * wf + af * fev.x;
    o.y = (acc0.y + acc1.y) * wf + af * fev.y;
    o.z = (acc0.z + acc1.z) * wf + af * fev.z;
    o.w = (acc0.w + acc1.w) * wf + af * fev.w;
    storeHalf4(hout + (size_t)node * 128 + lane * 4, o);
}

// ---------------- PPR diffusion hop (warp per dst node, 8-deep MLP) ----------------
__global__ void k_diff(const __half* __restrict__ hin, __half* __restrict__ hout,
                       const float* __restrict__ feat, const float* __restrict__ lg,
                       const float* __restrict__ lb, float* __restrict__ rst, int finalize) {
    int node = (blockIdx.x * blockDim.x + threadIdx.x) >> 5;
    int lane = threadIdx.x & 31;
    if (node >= Nn) return;
    const __half* fe16 = g_p16 + (size_t)2 * Nn * 128;
    int beg = g_rowptr[node], end = g_rowptr[node + 1];
    int h = lane >> 2;
    float4 a0 = make_float4(0.f, 0.f, 0.f, 0.f);
    float4 a1 = make_float4(0.f, 0.f, 0.f, 0.f);
    float4 a2 = make_float4(0.f, 0.f, 0.f, 0.f);
    float4 a3 = make_float4(0.f, 0.f, 0.f, 0.f);
    int p = beg;
    for (; p + 8 <= end; p += 8) {
        int s0 = g_esrc[p],     s1 = g_esrc[p + 1], s2 = g_esrc[p + 2], s3 = g_esrc[p + 3];
        int s4 = g_esrc[p + 4], s5 = g_esrc[p + 5], s6 = g_esrc[p + 6], s7 = g_esrc[p + 7];
        float w0 = __half2float(g_logits[p * 8 + h]);
        float w1 = __half2float(g_logits[(p + 1) * 8 + h]);
        float w2 = __half2float(g_logits[(p + 2) * 8 + h]);
        float w3 = __half2float(g_logits[(p + 3) * 8 + h]);
        float w4 = __half2float(g_logits[(p + 4) * 8 + h]);
        float w5 = __half2float(g_logits[(p + 5) * 8 + h]);
        float w6 = __half2float(g_logits[(p + 6) * 8 + h]);
        float w7 = __half2float(g_logits[(p + 7) * 8 + h]);
        uint2 u0 = *(const uint2*)(hin + (size_t)s0 * 128 + lane * 4);
        uint2 u1 = *(const uint2*)(hin + (size_t)s1 * 128 + lane * 4);
        uint2 u2 = *(const uint2*)(hin + (size_t)s2 * 128 + lane * 4);
        uint2 u3 = *(const uint2*)(hin + (size_t)s3 * 128 + lane * 4);
        uint2 u4 = *(const uint2*)(hin + (size_t)s4 * 128 + lane * 4);
        uint2 u5 = *(const uint2*)(hin + (size_t)s5 * 128 + lane * 4);
        uint2 u6 = *(const uint2*)(hin + (size_t)s6 * 128 + lane * 4);
        uint2 u7 = *(const uint2*)(hin + (size_t)s7 * 128 + lane * 4);
        accumh(a0, u0, w0); accumh(a1, u1, w1);
        accumh(a2, u2, w2); accumh(a3, u3, w3);
        accumh(a0, u4, w4); accumh(a1, u5, w5);
        accumh(a2, u6, w6); accumh(a3, u7, w7);
    }
    for (; p + 4 <= end; p += 4) {
        int s0 = g_esrc[p], s1 = g_esrc[p + 1], s2 = g_esrc[p + 2], s3 = g_esrc[p + 3];
        float w0 = __half2float(g_logits[p * 8 + h]);
        float w1 = __half2float(g_logits[(p + 1) * 8 + h]);
        float w2 = __half2float(g_logits[(p + 2) * 8 + h]);
        float w3 = __half2float(g_logits[(p + 3) * 8 + h]);
        uint2 u0 = *(const uint2*)(hin + (size_t)s0 * 128 + lane * 4);
        uint2 u1 = *(const uint2*)(hin + (size_t)s1 * 128 + lane * 4);
        uint2 u2 = *(const uint2*)(hin + (size_t)s2 * 128 + lane * 4);
        uint2 u3 = *(const uint2*)(hin + (size_t)s3 * 128 + lane * 4);
        accumh(a0, u0, w0); accumh(a1, u1, w1);
        accumh(a2, u2, w2); accumh(a3, u3, w3);
    }
    for (; p < end; p++) {
        int s0 = g_esrc[p];
        float w0 = __half2float(g_logits[p * 8 + h]);
        uint2 u0 = *(const uint2*)(hin + (size_t)s0 * 128 + lane * 4);
        accumh(a0, u0, w0);
    }
    float wf = g_invden[node * 8 + h] * (1.0f - ALPHA) * g_tailnorm[node];
    float4 fev = h4tof4(*(const uint2*)(fe16 + (size_t)node * 128 + lane * 4));
    float af = ALPHA * g_headnorm[node];
    float4 o;
    o.x = (a0.x + a1.x + a2.x + a3.x) * wf + af * fev.x;
    o.y = (a0.y + a1.y + a2.y + a3.y) * wf + af * fev.y;
    o.z = (a0.z + a1.z + a2.z + a3.z) * wf + af * fev.z;
    o.w = (a0.w + a1.w + a2.w + a3.w) * wf + af * fev.w;
    if (!finalize) {
        storeHalf4(hout + (size_t)node * 128 + lane * 4, o);
        return;
    }
    float4 fv = *(const float4*)(feat + (size_t)node * 128 + lane * 4);
    float4 v;
    v.x = o.x + fv.x; v.y = o.y + fv.y; v.z = o.z + fv.z; v.w = o.w + fv.w;
    *(float4*)(rst + (size_t)node * 128 + lane * 4) = v;
    float s  = v.x + v.y + v.z + v.w;
    float s2 = v.x * v.x + v.y * v.y + v.z * v.z + v.w * v.w;
    #pragma unroll
    for (int off = 16; off > 0; off >>= 1) {
        s  += __shfl_xor_sync(0xffffffffu, s, off);
        s2 += __shfl_xor_sync(0xffffffffu, s2, off);
    }
    float mu  = s * (1.0f / 128.0f);
    float var = s2 * (1.0f / 128.0f) - mu * mu;
    float inv = rsqrtf(var + 1e-5f);
    float4 gv = *(const float4*)(lg + lane * 4);
    float4 bv = *(const float4*)(lb + lane * 4);
    float4 o4;
    o4.x = (v.x - mu) * inv * gv.x + bv.x;
    o4.y = (v.y - mu) * inv * gv.y + bv.y;
    o4.z = (v.z - mu) * inv * gv.z + bv.z;
    o4.w = (v.w - mu) * inv * gv.w + bv.w;
    storeHalf4(g_x16 + (size_t)node * 128 + lane * 4, o4);
}

// ---------------- launch ----------------
static void* symv(const void* s) { void* p = nullptr; cudaGetSymbolAddress(&p, s); return p; }

extern "C" void kernel_launch(void* const* d_in, const int* in_sizes, int n_in,
                              void* d_out, int out_size) {
    const float* feat  = (const float*)d_in[0];
    const int*   src   = (const int*)d_in[1];
    const int*   dst   = (const int*)d_in[2];
    const float* w_head = (const float*)d_in[3];
    const float* w_tail = (const float*)d_in[4];
    const float* w_ent  = (const float*)d_in[5];
    const float* attn   = (const float*)d_in[6];
    const float* ln1_g  = (const float*)d_in[7];
    const float* ln1_b  = (const float*)d_in[8];
    const float* ln2_g  = (const float*)d_in[9];
    const float* ln2_b  = (const float*)d_in[10];
    const float* ff_w1  = (const float*)d_in[11];
    const float* ff_b1  = (const float*)d_in[12];
    const float* ff_w2  = (const float*)d_in[13];
    const float* ff_b2  = (const float*)d_in[14];
    int E = in_sizes[1];

    __half* p_x16  = (__half*)symv(g_x16);
    __half* p_pw   = (__half*)symv(g_pw16);
    __half* p_w1   = (__half*)symv(g_w116);
    __half* p_w2   = (__half*)symv(g_w216);
    __half* p_f1   = (__half*)symv(g_f1);
    __half* p_p16  = (__half*)symv(g_p16);
    __half* p_ha   = (__half*)symv(g_h16a);
    __half* p_hb   = (__half*)symv(g_h16b);
    float*  p_rst  = (float*)symv(g_rst);
    float*  out    = (float*)d_out;

    static int smemSet = 0;
    if (!smemSet) {
        cudaFuncSetAttribute(k_mma, cudaFuncAttributeMaxDynamicSharedMemorySize, MMA_SMEM_BYTES);
        smemSet = 1;
    }

    const int TB = 256;
    int gN  = (Nn + TB - 1) / TB;
    int gE  = (E + TB - 1) / TB;
    int gW  = (Nn * 32 + TB - 1) / TB;
    int gS1 = (Nn + 511) / 512;
    int gM  = (Nn + 127) / 128;

    // #1 weight convert + zero, #2 LN1, #3 hist — projection GEMM at #4 (ncu window)
    k_splitall<<<(230224 + 255) / 256, 256>>>(w_head, w_tail, w_ent, ff_w1, ff_w2);
    k_ln<<<gW, TB>>>(feat, ln1_g, ln1_b);
    k_hist<<<gE, TB>>>(src, dst, E);
    // #4: all 3 projections in one launch (pure fp16 outputs)
    k_mma<<<dim3(gM, 3), 256, MMA_SMEM_BYTES>>>(p_x16, p_pw,
                                128, 0, 128, 128 * 128, Nn * 128, 0,
                                nullptr, nullptr, nullptr, p_p16);
    // CSR build (rest)
    k_scan1<<<gS1, 512>>>();
    k_scan2<<<1, 128>>>();
    k_scan3ns<<<gN, TB>>>();
    k_scatter<<<gE, TB>>>(src, dst, E);

    // single-pass fused attention + softmax + hop0
    k_attnhop<<<gW, TB>>>(attn, p_ha);

    // hops 1-4 (hop 4 fuses rst + LN2)
    k_diff<<<gW, TB>>>(p_ha, p_hb, nullptr, nullptr, nullptr, nullptr, 0);
    k_diff<<<gW, TB>>>(p_hb, p_ha, nullptr, nullptr, nullptr, nullptr, 0);
    k_diff<<<gW, TB>>>(p_ha, p_hb, nullptr, nullptr, nullptr, nullptr, 0);
    k_diff<<<gW, TB>>>(p_hb, p_ha, feat, ln2_g, ln2_b, p_rst, 1);

    // FFN1: 4 col-slabs, relu+bias -> fp16 f1
    k_mma<<<dim3(gM, 4), 256, MMA_SMEM_BYTES>>>(p_x16, p_w1,
                                128, 1, 512, 128 * 128, 0, 128,
                                ff_b1, nullptr, nullptr, p_f1);
    // FFN2: K=512, + bias + residual -> fp32 out
    k_mma<<<dim3(gM, 1), 256, MMA_SMEM_BYTES>>>(p_f1, p_w2,
                                512, 2, 128, 0, 0, 0,
                                ff_b2, p_rst, out, nullptr);
}

// round 16
// speedup vs baseline: 1.5061x; 1.0211x over previous
#include <cuda_runtime.h>
#include <cuda_bf16.h>
#include <cuda_fp16.h>
#include <stdint.h>
#include <math.h>

#define Nn 50000
#define ALPHA 0.1f
#define SLOPE 0.2f
#define Ee 640000

// ---------------- device scratch ----------------
__device__ int   g_incnt[Nn];
__device__ int   g_outcnt[Nn];
__device__ int   g_cursor[Nn];
__device__ int   g_rowptr[Nn + 1];
__device__ int   g_boff[128];
__device__ int   g_bsums[128];
__device__ int   g_esrc[Ee];

__device__ __half g_x16[Nn * 128];          // LN1/LN2 output, fp16
__device__ __half g_p16[3 * Nn * 128];      // fh16 | ft16 | fe16 gather tables
__device__ __half g_h16a[Nn * 128];
__device__ __half g_h16b[Nn * 128];
__device__ float g_rst[Nn * 128];
__device__ __half g_f1[Nn * 512];           // FFN1 output, fp16
__device__ __half g_logits[Ee * 8];         // exp(e)*hn[src], fp16
__device__ float g_invden[Nn * 8];
__device__ float g_headnorm[Nn];
__device__ float g_tailnorm[Nn];

__device__ __half g_pw16[3 * 128 * 128];
__device__ __half g_w116[512 * 128];
__device__ __half g_w216[128 * 512];

// ---------------- weight convert (weights only) ----------------
__global__ void k_splitall(const float* __restrict__ wa, const float* __restrict__ wb,
                           const float* __restrict__ wc, const float* __restrict__ wd,
                           const float* __restrict__ we) {
    int i = blockIdx.x * blockDim.x + threadIdx.x;
    if (i >= 180224) return;
    const float* s; __half* hi; int off;
    if (i < 16384)        { s = wa; off = i;          hi = g_pw16; }
    else if (i < 32768)   { s = wb; off = i - 16384;  hi = g_pw16 + 16384; }
    else if (i < 49152)   { s = wc; off = i - 32768;  hi = g_pw16 + 32768; }
    else if (i < 114688)  { s = wd; off = i - 49152;  hi = g_w116; }
    else                  { s = we; off = i - 114688; hi = g_w216; }
    hi[off] = __float2half_rn(s[off]);
}

// ---------------- CSR build ----------------
__global__ void k_zero() {
    int i = blockIdx.x * blockDim.x + threadIdx.x;
    if (i < Nn) { g_incnt[i] = 0; g_outcnt[i] = 0; g_cursor[i] = 0; }
}
__global__ void k_hist(const int* __restrict__ src, const int* __restrict__ dst, int E) {
    int e = blockIdx.x * blockDim.x + threadIdx.x;
    if (e < E) {
        atomicAdd(&g_incnt[dst[e]], 1);
        atomicAdd(&g_outcnt[src[e]], 1);
    }
}
__global__ void k_scan1() {
    __shared__ int s[512];
    int t = threadIdx.x;
    int i = blockIdx.x * 512 + t;
    int v = (i < Nn) ? g_incnt[i] : 0;
    s[t] = v;
    __syncthreads();
    for (int off = 1; off < 512; off <<= 1) {
        int add = (t >= off) ? s[t - off] : 0;
        __syncthreads();
        s[t] += add;
        __syncthreads();
    }
    if (i < Nn) g_rowptr[i + 1] = s[t];
    if (t == 511) g_bsums[blockIdx.x] = s[511];
}
__global__ void k_scan2() {
    const int NB = (Nn + 511) / 512;
    __shared__ int s[128];
    int t = threadIdx.x;
    int v = (t < NB) ? g_bsums[t] : 0;
    s[t] = v;
    __syncthreads();
    for (int off = 1; off < 128; off <<= 1) {
        int add = (t >= off) ? s[t - off] : 0;
        __syncthreads();
        s[t] += add;
        __syncthreads();
    }
    g_boff[t] = s[t] - v;
}
__global__ void k_scan3ns() {
    int i = blockIdx.x * blockDim.x + threadIdx.x;
    if (i < Nn) {
        g_rowptr[i + 1] += g_boff[i >> 9];
        int od = g_outcnt[i]; if (od < 1) od = 1;
        int id = g_incnt[i];  if (id < 1) id = 1;
        g_headnorm[i] = rsqrtf((float)od);
        g_tailnorm[i] = sqrtf((float)id);
    }
    if (i == 0) g_rowptr[0] = 0;
}
__global__ void k_scatter(const int* __restrict__ src, const int* __restrict__ dst, int E) {
    int e = blockIdx.x * blockDim.x + threadIdx.x;
    if (e < E) {
        int d = dst[e];
        int pos = g_rowptr[d] + atomicAdd(&g_cursor[d], 1);
        g_esrc[pos] = src[e];
    }
}

// ---------------- helpers ----------------
__device__ __forceinline__ void storeHalf4(__half* p, float4 v) {
    __half2 a = __floats2half2_rn(v.x, v.y);
    __half2 b = __floats2half2_rn(v.z, v.w);
    uint2 u; u.x = *(unsigned*)&a; u.y = *(unsigned*)&b;
    *(uint2*)p = u;
}
__device__ __forceinline__ float4 h4tof4(uint2 u) {
    float2 f0 = __half22float2(*(__half2*)&u.x);
    float2 f1 = __half22float2(*(__half2*)&u.y);
    float4 r; r.x = f0.x; r.y = f0.y; r.z = f1.x; r.w = f1.y;
    return r;
}
__device__ __forceinline__ void accumh(float4& a, uint2 u, float w) {
    __half2 p0 = *(__half2*)&u.x;
    __half2 p1 = *(__half2*)&u.y;
    float2 f0 = __half22float2(p0);
    float2 f1 = __half22float2(p1);
    a.x = fmaf(f0.x, w, a.x); a.y = fmaf(f0.y, w, a.y);
    a.z = fmaf(f1.x, w, a.z); a.w = fmaf(f1.y, w, a.w);
}

// ---------------- LayerNorm -> fp16 (warp per node) ----------------
__global__ void k_ln(const float* __restrict__ in, const float* __restrict__ g,
                     const float* __restrict__ b) {
    int node = (blockIdx.x * blockDim.x + threadIdx.x) >> 5;
    int lane = threadIdx.x & 31;
    if (node >= Nn) return;
    float4 v = *(const float4*)(in + node * 128 + lane * 4);
    float s  = v.x + v.y + v.z + v.w;
    float s2 = v.x * v.x + v.y * v.y + v.z * v.z + v.w * v.w;
    #pragma unroll
    for (int o = 16; o > 0; o >>= 1) {
        s  += __shfl_xor_sync(0xffffffffu, s, o);
        s2 += __shfl_xor_sync(0xffffffffu, s2, o);
    }
    float mu  = s * (1.0f / 128.0f);
    float var = s2 * (1.0f / 128.0f) - mu * mu;
    float inv = rsqrtf(var + 1e-5f);
    float4 gv = *(const float4*)(g + lane * 4);
    float4 bv = *(const float4*)(b + lane * 4);
    float4 o4;
    o4.x = (v.x - mu) * inv * gv.x + bv.x;
    o4.y = (v.y - mu) * inv * gv.y + bv.y;
    o4.z = (v.z - mu) * inv * gv.z + bv.z;
    o4.w = (v.w - mu) * inv * gv.w + bv.w;
    storeHalf4(g_x16 + node * 128 + lane * 4, o4);
}

// ---------------- fp16 tensor-core GEMM (proven M128 config) ----------------
__device__ __forceinline__ void mma16816(float* c, const unsigned* a, unsigned b0, unsigned b1) {
    asm("mma.sync.aligned.m16n8k16.row.col.f32.f16.f16.f32 "
        "{%0,%1,%2,%3}, {%4,%5,%6,%7}, {%8,%9}, {%0,%1,%2,%3};"
        : "+f"(c[0]), "+f"(c[1]), "+f"(c[2]), "+f"(c[3])
        : "r"(a[0]), "r"(a[1]), "r"(a[2]), "r"(a[3]), "r"(b0), "r"(b1));
}
__device__ __forceinline__ void ldsm4(unsigned* r, const void* p) {
    unsigned a = (unsigned)__cvta_generic_to_shared(p);
    asm volatile("ldmatrix.sync.aligned.m8n8.x4.shared.b16 {%0,%1,%2,%3}, [%4];"
        : "=r"(r[0]), "=r"(r[1]), "=r"(r[2]), "=r"(r[3]) : "r"(a));
}
__device__ __forceinline__ void cpasync16(void* smem, const void* g, bool p) {
    unsigned sa = (unsigned)__cvta_generic_to_shared(smem);
    int sz = p ? 16 : 0;
    asm volatile("cp.async.cg.shared.global [%0], [%1], 16, %2;" :: "r"(sa), "l"(g), "r"(sz));
}
__device__ __forceinline__ void cpcommit() { asm volatile("cp.async.commit_group;"); }
template<int N> __device__ __forceinline__ void cpwait() {
    asm volatile("cp.async.wait_group %0;" :: "n"(N));
}

#define STAGES 4
#define STAGE_ELEMS (128 * 40)
#define MMA_SMEM_BYTES (STAGES * STAGE_ELEMS * 2 * 2)

// mode 0: O16[y] = half(acc)
// mode 1: O16 = half(relu(acc + e1[col]))
// mode 2: Cf = acc + e1[col] + e2[row*128+col]
__global__ void __launch_bounds__(256, 2) k_mma(
    const __half* __restrict__ A, const __half* __restrict__ W,
    int K, int mode, int ldc, int wyStride, int o16yStride, int colPerY,
    const float* __restrict__ e1, const float* __restrict__ e2,
    float* __restrict__ Cf, __half* __restrict__ O16)
{
    extern __shared__ __align__(16) __half sm[];
    __half* AsS = sm;
    __half* BsS = sm + STAGES * STAGE_ELEMS;

    const int t = threadIdx.x;
    const int lt = t & 31, wid = t >> 5;
    const int wm = wid & 3, wn = wid >> 2;
    const int r4 = lt >> 2, tig = lt & 3;
    const int row0 = blockIdx.x * 128;

    const __half* Wg = W + (size_t)blockIdx.y * wyStride;
    __half* C16 = O16 ? O16 + (size_t)blockIdx.y * o16yStride : O16;
    const int col0 = blockIdx.y * colPerY;

    const int NCH = K >> 5;

    float c[2][8][4];
    #pragma unroll
    for (int i = 0; i < 2; i++)
        #pragma unroll
        for (int j = 0; j < 8; j++)
            #pragma unroll
            for (int k = 0; k < 4; k++) c[i][j][k] = 0.f;

    auto loadChunk = [&](int cidx, int st) {
        int kc = cidx << 5;
        __half* Ab = AsS + st * STAGE_ELEMS;
        __half* Bb = BsS + st * STAGE_ELEMS;
        #pragma unroll
        for (int i = 0; i < 2; i++) {
            int lin = t + i * 256;
            int row = lin >> 2, q = lin & 3;
            int gr = row0 + row;
            cpasync16(Ab + row * 40 + q * 8, A + (size_t)gr * K + kc + q * 8, gr < Nn);
            cpasync16(Bb + row * 40 + q * 8, Wg + (size_t)row * K + kc + q * 8, true);
        }
    };

    loadChunk(0, 0); cpcommit();
    if (NCH > 1) { loadChunk(1, 1); } cpcommit();
    if (NCH > 2) { loadChunk(2, 2); } cpcommit();

    const int rb0 = wm * 32;
    for (int cc = 0; cc < NCH; cc++) {
        cpwait<2>();
        __syncthreads();
        if (cc + 3 < NCH)
            loadChunk(cc + 3, (cc + 3) & (STAGES - 1));
        cpcommit();
        const __half* Asb = AsS + (cc & (STAGES - 1)) * STAGE_ELEMS;
        const __half* Bsb = BsS + (cc & (STAGES - 1)) * STAGE_ELEMS;

        unsigned a0[2][4], a1[2][4];
        #pragma unroll
        for (int ks = 0; ks < 2; ks++) {
            ldsm4(a0[ks], Asb + (rb0 + (lt & 15)) * 40 + ks * 16 + ((lt >> 4) * 8));
            ldsm4(a1[ks], Asb + (rb0 + 16 + (lt & 15)) * 40 + ks * 16 + ((lt >> 4) * 8));
        }
        #pragma unroll
        for (int ks = 0; ks < 2; ks++) {
            #pragma unroll
            for (int ntp = 0; ntp < 4; ntp++) {
                unsigned br[4];
                int nrow = wn * 64 + ntp * 16 + ((lt >> 4) << 3) + (lt & 7);
                ldsm4(br, Bsb + nrow * 40 + ks * 16 + (((lt >> 3) & 1) * 8));
                mma16816(c[0][2 * ntp],     a0[ks], br[0], br[1]);
                mma16816(c[1][2 * ntp],     a1[ks], br[0], br[1]);
                mma16816(c[0][2 * ntp + 1], a0[ks], br[2], br[3]);
                mma16816(c[1][2 * ntp + 1], a1[ks], br[2], br[3]);
            }
        }
    }

    // epilogue
    #pragma unroll
    for (int mt = 0; mt < 2; mt++) {
        #pragma unroll
        for (int half = 0; half < 2; half++) {
            int r = row0 + wm * 32 + mt * 16 + r4 + half * 8;
            if (r >= Nn) continue;
            if (mode == 0) {
                #pragma unroll
                for (int nt = 0; nt < 8; nt++) {
                    int col = wn * 64 + nt * 8 + tig * 2;
                    *(__half2*)(C16 + (size_t)r * ldc + col) =
                        __floats2half2_rn(c[mt][nt][half * 2], c[mt][nt][half * 2 + 1]);
                }
            } else if (mode == 1) {
                #pragma unroll
                for (int nt = 0; nt < 8; nt++) {
                    int col = col0 + wn * 64 + nt * 8 + tig * 2;
                    float v0 = fmaxf(c[mt][nt][half * 2] + e1[col], 0.f);
                    float v1 = fmaxf(c[mt][nt][half * 2 + 1] + e1[col + 1], 0.f);
                    *(__half2*)(C16 + (size_t)r * ldc + col) = __floats2half2_rn(v0, v1);
                }
            } else {
                #pragma unroll
                for (int nt = 0; nt < 8; nt++) {
                    int col = wn * 64 + nt * 8 + tig * 2;
                    float2 o;
                    o.x = c[mt][nt][half * 2] + e1[col] + e2[(size_t)r * 128 + col];
                    o.y = c[mt][nt][half * 2 + 1] + e1[col + 1] + e2[(size_t)r * 128 + col + 1];
                    *(float2*)(Cf + (size_t)r * ldc + col) = o;
                }
            }
        }
    }
}

// ---------------- fused attention + softmax + hop0, single pass, half2 math ----------------
__global__ void k_attnhop(const float* __restrict__ attn, __half* __restrict__ hout) {
    int node = (blockIdx.x * blockDim.x + threadIdx.x) >> 5;
    int lane = threadIdx.x & 31;
    if (node >= Nn) return;
    const __half* fh16 = g_p16;
    const __half* ft16 = g_p16 + (size_t)Nn * 128;
    const __half* fe16 = g_p16 + (size_t)2 * Nn * 128;
    int beg = g_rowptr[node], end = g_rowptr[node + 1];
    int h = lane >> 2;
    uint2 ftu = *(const uint2*)(ft16 + (size_t)node * 128 + lane * 4);
    __half2 fta = *(__half2*)&ftu.x;
    __half2 ftb = *(__half2*)&ftu.y;
    const __half2 sl2 = __float2half2_rn(SLOPE);
    float4 av = *(const float4*)(attn + lane * 4);
    float hnn = g_headnorm[node];
    float scale = log1pf((float)g_incnt[node]) * (1.0f / 16.0f) * hnn;
    float4 acc0 = make_float4(0.f, 0.f, 0.f, 0.f);
    float4 acc1 = make_float4(0.f, 0.f, 0.f, 0.f);
    float sum = 0.f;
    int p = beg;
    for (; p + 2 <= end; p += 2) {
        int s0 = g_esrc[p];
        int s1 = g_esrc[p + 1];
        float hs0 = g_headnorm[s0], hs1 = g_headnorm[s1];
        uint2 u0 = *(const uint2*)(fh16 + (size_t)s0 * 128 + lane * 4);
        uint2 u1 = *(const uint2*)(fh16 + (size_t)s1 * 128 + lane * 4);
        uint2 f0 = *(const uint2*)(fe16 + (size_t)s0 * 128 + lane * 4);
        uint2 f1 = *(const uint2*)(fe16 + (size_t)s1 * 128 + lane * 4);
        __half2 p0a = __hmul2(*(__half2*)&u0.x, fta);
        __half2 p0b = __hmul2(*(__half2*)&u0.y, ftb);
        __half2 p1a = __hmul2(*(__half2*)&u1.x, fta);
        __half2 p1b = __hmul2(*(__half2*)&u1.y, ftb);
        p0a = __hmax2(p0a, __hmul2(p0a, sl2));
        p0b = __hmax2(p0b, __hmul2(p0b, sl2));
        p1a = __hmax2(p1a, __hmul2(p1a, sl2));
        p1b = __hmax2(p1b, __hmul2(p1b, sl2));
        float2 q0a = __half22float2(p0a), q0b = __half22float2(p0b);
        float2 q1a = __half22float2(p1a), q1b = __half22float2(p1b);
        float ts0 = q0a.x * av.x + q0a.y * av.y + q0b.x * av.z + q0b.y * av.w;
        float ts1 = q1a.x * av.x + q1a.y * av.y + q1b.x * av.z + q1b.y * av.w;
        ts0 += __shfl_xor_sync(0xffffffffu, ts0, 1);
        ts1 += __shfl_xor_sync(0xffffffffu, ts1, 1);
        ts0 += __shfl_xor_sync(0xffffffffu, ts0, 2);
        ts1 += __shfl_xor_sync(0xffffffffu, ts1, 2);
        float w0 = __expf(ts0 * scale * hs0);
        float w1 = __expf(ts1 * scale * hs1);
        sum += w0 + w1;
        float wh0 = w0 * hs0, wh1 = w1 * hs1;
        if ((lane & 3) == 0) {
            g_logits[p * 8 + h] = __float2half_rn(wh0);
            g_logits[(p + 1) * 8 + h] = __float2half_rn(wh1);
        }
        accumh(acc0, f0, wh0);
        accumh(acc1, f1, wh1);
    }
    if (p < end) {
        int s0 = g_esrc[p];
        float hs0 = g_headnorm[s0];
        uint2 u0 = *(const uint2*)(fh16 + (size_t)s0 * 128 + lane * 4);
        uint2 f0 = *(const uint2*)(fe16 + (size_t)s0 * 128 + lane * 4);
        __half2 p0a = __hmul2(*(__half2*)&u0.x, fta);
        __half2 p0b = __hmul2(*(__half2*)&u0.y, ftb);
        p0a = __hmax2(p0a, __hmul2(p0a, sl2));
        p0b = __hmax2(p0b, __hmul2(p0b, sl2));
        float2 q0a = __half22float2(p0a), q0b = __half22float2(p0b);
        float ts = q0a.x * av.x + q0a.y * av.y + q0b.x * av.z + q0b.y * av.w;
        ts += __shfl_xor_sync(0xffffffffu, ts, 1);
        ts += __shfl_xor_sync(0xffffffffu, ts, 2);
        float w0 = __expf(ts * scale * hs0);
        sum += w0;
        float wh0 = w0 * hs0;
        if ((lane & 3) == 0) g_logits[p * 8 + h] = __float2half_rn(wh0);
        accumh(acc0, f0, wh0);
    }
    float inv = 1.0f / sum;
    if ((lane & 3) == 0) g_invden[node * 8 + h] = inv;
    float wf = inv * (1.0f - ALPHA) * g_tailnorm[node];
    float4 fev = h4tof4(*(const uint2*)(fe16 + (size_t)node * 128 + lane * 4));
    float af = ALPHA * hnn;
    float4 o;
    o.x = (acc0.x + acc1.x) * wf + af * fev.x;
    o.y = (acc0.y + acc1.y) * wf + af * fev.y;
    o.z = (acc0.z + acc1.z) * wf + af * fev.z;
    o.w = (acc0.w + acc1.w) * wf + af * fev.w;
    storeHalf4(hout + (size_t)node * 128 + lane * 4, o);
}

// ---------------- PPR diffusion hop (warp per dst node, 8-deep MLP) ----------------
__global__ void k_diff(const __half* __restrict__ hin, __half* __restrict__ hout,
                       const float* __restrict__ feat, const float* __restrict__ lg,
                       const float* __restrict__ lb, float* __restrict__ rst, int finalize) {
    int node = (blockIdx.x * blockDim.x + threadIdx.x) >> 5;
    int lane = threadIdx.x & 31;
    if (node >= Nn) return;
    const __half* fe16 = g_p16 + (size_t)2 * Nn * 128;
    int beg = g_rowptr[node], end = g_rowptr[node + 1];
    int h = lane >> 2;
    float4 a0 = make_float4(0.f, 0.f, 0.f, 0.f);
    float4 a1 = make_float4(0.f, 0.f, 0.f, 0.f);
    float4 a2 = make_float4(0.f, 0.f, 0.f, 0.f);
    float4 a3 = make_float4(0.f, 0.f, 0.f, 0.f);
    int p = beg;
    for (; p + 8 <= end; p += 8) {
        int s0 = g_esrc[p],     s1 = g_esrc[p + 1], s2 = g_esrc[p + 2], s3 = g_esrc[p + 3];
        int s4 = g_esrc[p + 4], s5 = g_esrc[p + 5], s6 = g_esrc[p + 6], s7 = g_esrc[p + 7];
        float w0 = __half2float(g_logits[p * 8 + h]);
        float w1 = __half2float(g_logits[(p + 1) * 8 + h]);
        float w2 = __half2float(g_logits[(p + 2) * 8 + h]);
        float w3 = __half2float(g_logits[(p + 3) * 8 + h]);
        float w4 = __half2float(g_logits[(p + 4) * 8 + h]);
        float w5 = __half2float(g_logits[(p + 5) * 8 + h]);
        float w6 = __half2float(g_logits[(p + 6) * 8 + h]);
        float w7 = __half2float(g_logits[(p + 7) * 8 + h]);
        uint2 u0 = *(const uint2*)(hin + (size_t)s0 * 128 + lane * 4);
        uint2 u1 = *(const uint2*)(hin + (size_t)s1 * 128 + lane * 4);
        uint2 u2 = *(const uint2*)(hin + (size_t)s2 * 128 + lane * 4);
        uint2 u3 = *(const uint2*)(hin + (size_t)s3 * 128 + lane * 4);
        uint2 u4 = *(const uint2*)(hin + (size_t)s4 * 128 + lane * 4);
        uint2 u5 = *(const uint2*)(hin + (size_t)s5 * 128 + lane * 4);
        uint2 u6 = *(const uint2*)(hin + (size_t)s6 * 128 + lane * 4);
        uint2 u7 = *(const uint2*)(hin + (size_t)s7 * 128 + lane * 4);
        accumh(a0, u0, w0); accumh(a1, u1, w1);
        accumh(a2, u2, w2); accumh(a3, u3, w3);
        accumh(a0, u4, w4); accumh(a1, u5, w5);
        accumh(a2, u6, w6); accumh(a3, u7, w7);
    }
    for (; p + 4 <= end; p += 4) {
        int s0 = g_esrc[p], s1 = g_esrc[p + 1], s2 = g_esrc[p + 2], s3 = g_esrc[p + 3];
        float w0 = __half2float(g_logits[p * 8 + h]);
        float w1 = __half2float(g_logits[(p + 1) * 8 + h]);
        float w2 = __half2float(g_logits[(p + 2) * 8 + h]);
        float w3 = __half2float(g_logits[(p + 3) * 8 + h]);
        uint2 u0 = *(const uint2*)(hin + (size_t)s0 * 128 + lane * 4);
        uint2 u1 = *(const uint2*)(hin + (size_t)s1 * 128 + lane * 4);
        uint2 u2 = *(const uint2*)(hin + (size_t)s2 * 128 + lane * 4);
        uint2 u3 = *(const uint2*)(hin + (size_t)s3 * 128 + lane * 4);
        accumh(a0, u0, w0); accumh(a1, u1, w1);
        accumh(a2, u2, w2); accumh(a3, u3, w3);
    }
    for (; p < end; p++) {
        int s0 = g_esrc[p];
        float w0 = __half2float(g_logits[p * 8 + h]);
        uint2 u0 = *(const uint2*)(hin + (size_t)s0 * 128 + lane * 4);
        accumh(a0, u0, w0);
    }
    float wf = g_invden[node * 8 + h] * (1.0f - ALPHA) * g_tailnorm[node];
    float4 fev = h4tof4(*(const uint2*)(fe16 + (size_t)node * 128 + lane * 4));
    float af = ALPHA * g_headnorm[node];
    float4 o;
    o.x = (a0.x + a1.x + a2.x + a3.x) * wf + af * fev.x;
    o.y = (a0.y + a1.y + a2.y + a3.y) * wf + af * fev.y;
    o.z = (a0.z + a1.z + a2.z + a3.z) * wf + af * fev.z;
    o.w = (a0.w + a1.w + a2.w + a3.w) * wf + af * fev.w;
    if (!finalize) {
        storeHalf4(hout + (size_t)node * 128 + lane * 4, o);
        return;
    }
    float4 fv = *(const float4*)(feat + (size_t)node * 128 + lane * 4);
    float4 v;
    v.x = o.x + fv.x; v.y = o.y + fv.y; v.z = o.z + fv.z; v.w = o.w + fv.w;
    *(float4*)(rst + (size_t)node * 128 + lane * 4) = v;
    float s  = v.x + v.y + v.z + v.w;
    float s2 = v.x * v.x + v.y * v.y + v.z * v.z + v.w * v.w;
    #pragma unroll
    for (int off = 16; off > 0; off >>= 1) {
        s  += __shfl_xor_sync(0xffffffffu, s, off);
        s2 += __shfl_xor_sync(0xffffffffu, s2, off);
    }
    float mu  = s * (1.0f / 128.0f);
    float var = s2 * (1.0f / 128.0f) - mu * mu;
    float inv = rsqrtf(var + 1e-5f);
    float4 gv = *(const float4*)(lg + lane * 4);
    float4 bv = *(const float4*)(lb + lane * 4);
    float4 o4;
    o4.x = (v.x - mu) * inv * gv.x + bv.x;
    o4.y = (v.y - mu) * inv * gv.y + bv.y;
    o4.z = (v.z - mu) * inv * gv.z + bv.z;
    o4.w = (v.w - mu) * inv * gv.w + bv.w;
    storeHalf4(g_x16 + (size_t)node * 128 + lane * 4, o4);
}

// ---------------- launch ----------------
static void* symv(const void* s) { void* p = nullptr; cudaGetSymbolAddress(&p, s); return p; }

extern "C" void kernel_launch(void* const* d_in, const int* in_sizes, int n_in,
                              void* d_out, int out_size) {
    const float* feat  = (const float*)d_in[0];
    const int*   src   = (const int*)d_in[1];
    const int*   dst   = (const int*)d_in[2];
    const float* w_head = (const float*)d_in[3];
    const float* w_tail = (const float*)d_in[4];
    const float* w_ent  = (const float*)d_in[5];
    const float* attn   = (const float*)d_in[6];
    const float* ln1_g  = (const float*)d_in[7];
    const float* ln1_b  = (const float*)d_in[8];
    const float* ln2_g  = (const float*)d_in[9];
    const float* ln2_b  = (const float*)d_in[10];
    const float* ff_w1  = (const float*)d_in[11];
    const float* ff_b1  = (const float*)d_in[12];
    const float* ff_w2  = (const float*)d_in[13];
    const float* ff_b2  = (const float*)d_in[14];
    int E = in_sizes[1];

    __half* p_x16  = (__half*)symv(g_x16);
    __half* p_pw   = (__half*)symv(g_pw16);
    __half* p_w1   = (__half*)symv(g_w116);
    __half* p_w2   = (__half*)symv(g_w216);
    __half* p_f1   = (__half*)symv(g_f1);
    __half* p_p16  = (__half*)symv(g_p16);
    __half* p_ha   = (__half*)symv(g_h16a);
    __half* p_hb   = (__half*)symv(g_h16b);
    float*  p_rst  = (float*)symv(g_rst);
    float*  out    = (float*)d_out;

    static int inited = 0;
    static cudaStream_t sA, sB;
    static cudaEvent_t evF, evA, evB;
    if (!inited) {
        cudaFuncSetAttribute(k_mma, cudaFuncAttributeMaxDynamicSharedMemorySize, MMA_SMEM_BYTES);
        cudaStreamCreateWithFlags(&sA, cudaStreamNonBlocking);
        cudaStreamCreateWithFlags(&sB, cudaStreamNonBlocking);
        cudaEventCreateWithFlags(&evF, cudaEventDisableTiming);
        cudaEventCreateWithFlags(&evA, cudaEventDisableTiming);
        cudaEventCreateWithFlags(&evB, cudaEventDisableTiming);
        inited = 1;
    }

    const int TB = 256;
    int gN  = (Nn + TB - 1) / TB;
    int gE  = (E + TB - 1) / TB;
    int gW  = (Nn * 32 + TB - 1) / TB;
    int gS1 = (Nn + 511) / 512;
    int gM  = (Nn + 127) / 128;

    // fork: two parallel front chains
    cudaEventRecord(evF, 0);
    cudaStreamWaitEvent(sA, evF, 0);
    cudaStreamWaitEvent(sB, evF, 0);

    // chain A (sA): weight convert -> LN1 -> projection GEMM
    k_splitall<<<(180224 + 255) / 256, 256, 0, sA>>>(w_head, w_tail, w_ent, ff_w1, ff_w2);
    k_ln<<<gW, TB, 0, sA>>>(feat, ln1_g, ln1_b);
    k_mma<<<dim3(gM, 3), 256, MMA_SMEM_BYTES, sA>>>(p_x16, p_pw,
                                128, 0, 128, 128 * 128, Nn * 128, 0,
                                nullptr, nullptr, nullptr, p_p16);
    cudaEventRecord(evA, sA);

    // chain B (sB): CSR build
    k_zero<<<gN, TB, 0, sB>>>();
    k_hist<<<gE, TB, 0, sB>>>(src, dst, E);
    k_scan1<<<gS1, 512, 0, sB>>>();
    k_scan2<<<1, 128, 0, sB>>>();
    k_scan3ns<<<gN, TB, 0, sB>>>();
    k_scatter<<<gE, TB, 0, sB>>>(src, dst, E);
    cudaEventRecord(evB, sB);

    // join
    cudaStreamWaitEvent(0, evA, 0);
    cudaStreamWaitEvent(0, evB, 0);

    // single-pass fused attention + softmax + hop0
    k_attnhop<<<gW, TB>>>(attn, p_ha);

    // hops 1-4 (hop 4 fuses rst + LN2)
    k_diff<<<gW, TB>>>(p_ha, p_hb, nullptr, nullptr, nullptr, nullptr, 0);
    k_diff<<<gW, TB>>>(p_hb, p_ha, nullptr, nullptr, nullptr, nullptr, 0);
    k_diff<<<gW, TB>>>(p_ha, p_hb, nullptr, nullptr, nullptr, nullptr, 0);
    k_diff<<<gW, TB>>>(p_hb, p_ha, feat, ln2_g, ln2_b, p_rst, 1);

    // FFN1: 4 col-slabs, relu+bias -> fp16 f1
    k_mma<<<dim3(gM, 4), 256, MMA_SMEM_BYTES>>>(p_x16, p_w1,
                                128, 1, 512, 128 * 128, 0, 128,
                                ff_b1, nullptr, nullptr, p_f1);
    // FFN2: K=512, + bias + residual -> fp32 out
    k_mma<<<dim3(gM, 1), 256, MMA_SMEM_BYTES>>>(p_f1, p_w2,
                                512, 2, 128, 0, 0, 0,
                                ff_b2, p_rst, out, nullptr);
}